// round 16
// baseline (speedup 1.0000x reference)
#include <cuda_runtime.h>
#include <math.h>
#include <stdint.h>

#define BSZ 16
#define NN 768
#define INDIM 16
#define HID 64
#define EMB 128
#define NH 8
#define BN (BSZ*NN)        // 12288
#define FDIM (NH*HID)      // 512
#define BH (BSZ*NH)        // 128
#define BHN (BH*NN)        // 98304
#define CH 48
#define NCH 16             // CH*NCH = 768
#define PAD 20             // smem row stride (floats): conflict-free, no swizzle

// ---- static scratch ----
__device__ float g_h0 [BN*HID];
__device__ float g_Wh [BN*FDIM];
__device__ float g_hc1[BN*FDIM];
__device__ float g_hc2[BN*FDIM];
__device__ float g_s1[BHN], g_s2[BHN];
__device__ int   g_kofn[BHN];
__device__ float g_E1[BHN], g_F1[BHN], g_ivd[BHN];
__device__ float g_PreF[(size_t)BH*(NN+1)*HID];
__device__ float g_SufE[(size_t)BH*(NN+1)*HID];
__device__ float g_B0t[FDIM*HID];
__device__ float g_B1t[FDIM*FDIM];
__device__ float g_pwT[EMB*FDIM];

// ===================== HMMA tf32 GEMM (+ fused score) =====================
__device__ __forceinline__ uint32_t smem_u32(const void* p) {
    uint32_t a;
    asm("{ .reg .u64 t; cvta.to.shared.u64 t, %1; cvt.u32.u64 %0, t; }" : "=r"(a) : "l"(p));
    return a;
}
__device__ __forceinline__ uint32_t f2tf(float x) {
    uint32_t u; asm("cvt.rna.tf32.f32 %0, %1;" : "=r"(u) : "f"(x)); return u;
}
__device__ __forceinline__ float rnd_tf32(float x) {
    return __uint_as_float(f2tf(x));
}
__device__ __forceinline__ void mma_tf32(float* d, const uint32_t* a, const uint32_t* b) {
    asm volatile("mma.sync.aligned.m16n8k8.row.col.f32.tf32.tf32.f32 "
                 "{%0,%1,%2,%3}, {%4,%5,%6,%7}, {%8,%9}, {%0,%1,%2,%3};"
                 : "+f"(d[0]), "+f"(d[1]), "+f"(d[2]), "+f"(d[3])
                 : "r"(a[0]), "r"(a[1]), "r"(a[2]), "r"(a[3]), "r"(b[0]), "r"(b[1]));
}
#define CP16(dst, src) \
    asm volatile("cp.async.ca.shared.global [%0], [%1], 16;" :: "r"(dst), "l"(src) : "memory")
#define CP_COMMIT()  asm volatile("cp.async.commit_group;" ::: "memory")
#define CP_WAIT0()   asm volatile("cp.async.wait_group 0;" ::: "memory")

// CTA tile 128x128, 8 warps (4m x 2n), warp tile 32x64, BK=16.
// Operands PRE-ROUNDED tf32. K-accumulation sequence identical to prior
// version (same ordered k8 HMMA chain) -> bitwise-identical output.
__global__ __launch_bounds__(256)
void tf32_gemm(const float* __restrict__ A, const float* __restrict__ Bt,
               const float* __restrict__ bias, float* __restrict__ C,
               int N, int K,
               const float* __restrict__ att, float* __restrict__ s1out,
               float* __restrict__ s2out) {
    __shared__ float As[2][128 * PAD];
    __shared__ float Bs[2][128 * PAD];
    __shared__ float sp1[128 * 2], sp2[128 * 2];   // [row][head-within-tile]
    const int tid = threadIdx.x;
    const int wid = tid >> 5, lane = tid & 31;
    const int r = lane >> 2, cc = lane & 3;
    const int warp_m = (wid & 3) * 32, warp_n = (wid >> 2) * 64;
    const int m0 = blockIdx.x * 128, n0 = blockIdx.y * 128;

    sp1[tid] = 0.f; sp2[tid] = 0.f;

    uint32_t asb[2] = { smem_u32(&As[0][0]), smem_u32(&As[1][0]) };
    uint32_t bsb[2] = { smem_u32(&Bs[0][0]), smem_u32(&Bs[1][0]) };

    float acc[2][8][4] = {};
    const int NC = K >> 4;

    {   // stage chunk 0: 128 rows x 16 floats = 512 16B chunks per matrix
#pragma unroll
        for (int j = 0; j < 2; j++) {
            int u = tid + j * 256, row = u >> 2, ch = u & 3;
            CP16(asb[0] + (uint32_t)(row * PAD + ch * 4) * 4,
                 A + (size_t)(m0 + row) * K + ch * 4);
            CP16(bsb[0] + (uint32_t)(row * PAD + ch * 4) * 4,
                 Bt + (size_t)(n0 + row) * K + ch * 4);
        }
        CP_COMMIT();
    }

    for (int i = 0; i < NC; i++) {
        CP_WAIT0();
        __syncthreads();
        if (i + 1 < NC) {
            int nb = (i + 1) & 1, kc = (i + 1) * 16;
#pragma unroll
            for (int j = 0; j < 2; j++) {
                int u = tid + j * 256, row = u >> 2, ch = u & 3;
                CP16(asb[nb] + (uint32_t)(row * PAD + ch * 4) * 4,
                     A + (size_t)(m0 + row) * K + kc + ch * 4);
                CP16(bsb[nb] + (uint32_t)(row * PAD + ch * 4) * 4,
                     Bt + (size_t)(n0 + row) * K + kc + ch * 4);
            }
            CP_COMMIT();
        }
        const uint32_t* as = (const uint32_t*)As[i & 1];
        const uint32_t* bs = (const uint32_t*)Bs[i & 1];
#pragma unroll
        for (int ks = 0; ks < 2; ks++) {
            uint32_t af[2][4], bf[8][2];
#pragma unroll
            for (int mt = 0; mt < 2; mt++) {
                int rb = warp_m + mt * 16 + r;
                af[mt][0] = as[rb * PAD + ks * 8 + cc];
                af[mt][1] = as[(rb + 8) * PAD + ks * 8 + cc];
                af[mt][2] = as[rb * PAD + ks * 8 + cc + 4];
                af[mt][3] = as[(rb + 8) * PAD + ks * 8 + cc + 4];
            }
#pragma unroll
            for (int nt = 0; nt < 8; nt++) {
                int nb = warp_n + nt * 8 + r;
                bf[nt][0] = bs[nb * PAD + ks * 8 + cc];
                bf[nt][1] = bs[nb * PAD + ks * 8 + cc + 4];
            }
#pragma unroll
            for (int mt = 0; mt < 2; mt++)
#pragma unroll
                for (int nt = 0; nt < 8; nt++)
                    mma_tf32(acc[mt][nt], af[mt], bf[nt]);
        }
        __syncthreads();
    }

    // C store
#pragma unroll
    for (int mt = 0; mt < 2; mt++) {
#pragma unroll
        for (int nt = 0; nt < 8; nt++) {
            int row = m0 + warp_m + mt * 16 + r;
            int col = n0 + warp_n + nt * 8 + cc * 2;
            float bx = 0.f, by = 0.f;
            if (bias) { bx = bias[col]; by = bias[col + 1]; }
            float2 v0 = { acc[mt][nt][0] + bx, acc[mt][nt][1] + by };
            float2 v1 = { acc[mt][nt][2] + bx, acc[mt][nt][3] + by };
            *(float2*)&C[(size_t)row * N + col] = v0;
            *(float2*)&C[(size_t)(row + 8) * N + col] = v1;
        }
    }

    // fused score: warp's 64 cols = one head; tile spans 2 heads
    if (att) {
        int hh = warp_n >> 6;                 // 0 or 1 within tile
        int h = (n0 >> 6) + hh;
        const float* a1 = att + h * 2 * HID;
        const float* a2 = a1 + HID;
#pragma unroll
        for (int mt = 0; mt < 2; mt++) {
            float p1a = 0.f, p2a = 0.f, p1b = 0.f, p2b = 0.f;
#pragma unroll
            for (int nt = 0; nt < 8; nt++) {
                int col = nt * 8 + cc * 2;    // col within head (0..63)
                float a1x = a1[col], a1y = a1[col + 1];
                float a2x = a2[col], a2y = a2[col + 1];
                p1a += acc[mt][nt][0] * a1x + acc[mt][nt][1] * a1y;
                p2a += acc[mt][nt][0] * a2x + acc[mt][nt][1] * a2y;
                p1b += acc[mt][nt][2] * a1x + acc[mt][nt][3] * a1y;
                p2b += acc[mt][nt][2] * a2x + acc[mt][nt][3] * a2y;
            }
#pragma unroll
            for (int off = 1; off <= 2; off <<= 1) {
                p1a += __shfl_xor_sync(0xffffffffu, p1a, off);
                p2a += __shfl_xor_sync(0xffffffffu, p2a, off);
                p1b += __shfl_xor_sync(0xffffffffu, p1b, off);
                p2b += __shfl_xor_sync(0xffffffffu, p2b, off);
            }
            if (cc == 0) {
                int lr = warp_m + mt * 16 + r;
                atomicAdd(&sp1[lr * 2 + hh], p1a);     atomicAdd(&sp2[lr * 2 + hh], p2a);
                atomicAdd(&sp1[(lr + 8) * 2 + hh], p1b); atomicAdd(&sp2[(lr + 8) * 2 + hh], p2b);
            }
        }
        __syncthreads();
        int row = tid >> 1, hh2 = tid & 1;
        int gr = m0 + row;
        int b2 = gr / NN, n2 = gr % NN;
        int bh2 = b2 * NH + (n0 >> 6) + hh2;
        s1out[bh2 * NN + n2] = sp1[row * 2 + hh2];
        s2out[bh2 * NN + n2] = sp2[row * 2 + hh2];
    }
}

// ===================== non-GEMM kernels =====================

// Weights stored PRE-ROUNDED to tf32 bit patterns.
__global__ void prep_B(const float* __restrict__ w0, const float* __restrict__ w1,
                       const float* __restrict__ pw) {
    int i0 = blockIdx.x * blockDim.x + threadIdx.x;
    int stride = gridDim.x * blockDim.x;
    for (int i = i0; i < FDIM*HID; i += stride) {
        int n = i / HID, f = i % HID;
        g_B0t[i] = rnd_tf32(w0[(n / HID) * (HID*HID) + f * HID + (n % HID)]);
    }
    for (int i = i0; i < FDIM*FDIM; i += stride) {
        int n = i / FDIM, f = i % FDIM;
        g_B1t[i] = rnd_tf32(w1[(n / HID) * (FDIM*HID) + f * HID + (n % HID)]);
    }
    for (int i = i0; i < EMB*FDIM; i += stride) {
        int n = i / FDIM, k = i % FDIM;
        g_pwT[i] = rnd_tf32(pw[k * EMB + n]);
    }
}

// small fp32 SGEMM for the input projection (K=16); output PRE-ROUNDED.
__global__ void sgemm(const float* __restrict__ A, const float* __restrict__ B,
                      const float* __restrict__ bias, float* __restrict__ C,
                      int M, int N, int K) {
    __shared__ float As[16][64];
    __shared__ float Bs[16][64];
    int tid = threadIdx.x;
    int m0 = blockIdx.x * 64, n0 = blockIdx.y * 64;
    int tx = tid & 15, ty = tid >> 4;
    int arow = tid >> 2, acol = (tid & 3) * 4;
    int brow = tid >> 4, bcol = (tid & 15) * 4;
    float acc[4][4] = {};
    for (int kc = 0; kc < K; kc += 16) {
        float4 av = *(const float4*)&A[(size_t)(m0 + arow) * K + kc + acol];
        As[acol+0][arow] = av.x; As[acol+1][arow] = av.y;
        As[acol+2][arow] = av.z; As[acol+3][arow] = av.w;
        *(float4*)&Bs[brow][bcol] = *(const float4*)&B[(size_t)(kc + brow) * N + n0 + bcol];
        __syncthreads();
#pragma unroll
        for (int k = 0; k < 16; k++) {
            float4 a4 = *(float4*)&As[k][ty*4];
            float4 b4 = *(float4*)&Bs[k][tx*4];
            float a[4] = {a4.x, a4.y, a4.z, a4.w};
            float b[4] = {b4.x, b4.y, b4.z, b4.w};
#pragma unroll
            for (int i = 0; i < 4; i++)
#pragma unroll
                for (int j = 0; j < 4; j++) acc[i][j] += a[i] * b[j];
        }
        __syncthreads();
    }
#pragma unroll
    for (int i = 0; i < 4; i++) {
        int m = m0 + ty*4 + i, n = n0 + tx*4;
        float4 v = {rnd_tf32(acc[i][0] + bias[n]),   rnd_tf32(acc[i][1] + bias[n+1]),
                    rnd_tf32(acc[i][2] + bias[n+2]), rnd_tf32(acc[i][3] + bias[n+3])};
        *(float4*)&C[(size_t)m * N + n] = v;
    }
}

// Fused: per (b,h) u64-bitonic sort + E2/F2 + scans (smem) + per-n
// k/E1/F1/ivd precompute, then 16-chunk interleaved PreF/SufE table sweeps.
__global__ __launch_bounds__(1024)
void prep_scan(const float* __restrict__ s2, const float* __restrict__ s1,
               const float* __restrict__ Wh) {
    __shared__ unsigned long long sv[1024];
    __shared__ float fe[NN], ff[NN], s2c[NN];
    __shared__ float sF2[NN+1], sE2[NN+1];
    __shared__ int   perm[NN];
    __shared__ float wsE[32], wsF[32];
    __shared__ float chF[NCH*HID], chE[NCH*HID];
    const int bh = blockIdx.x, tid = threadIdx.x;
    const int lane = tid & 31, wrp = tid >> 5;
    const int h = bh % NH, b = bh / NH;

    {
        int i = tid;
        if (i < NN) {
            uint32_t bt = __float_as_uint(s2[bh*NN + i]);
            uint32_t key = (bt & 0x80000000u) ? ~bt : (bt | 0x80000000u);
            sv[i] = ((unsigned long long)key << 32) | (unsigned)i;
        } else sv[i] = 0xFFFFFFFFFFFFFFFFull;
    }
    __syncthreads();
    for (int k = 2; k <= 1024; k <<= 1) {
        for (int j = k >> 1; j > 0; j >>= 1) {
            int i = tid;
            int ixj = i ^ j;
            if (ixj > i) {
                bool up = ((i & k) == 0);
                unsigned long long a = sv[i], bb = sv[ixj];
                if ((a > bb) == up) { sv[i] = bb; sv[ixj] = a; }
            }
            __syncthreads();
        }
    }
    float mx;
    {
        uint32_t keyN = (uint32_t)(sv[NN-1] >> 32);
        uint32_t bt = (keyN & 0x80000000u) ? (keyN & 0x7FFFFFFFu) : ~keyN;
        mx = __uint_as_float(bt);
    }
    if (tid < NN) {
        int i = tid;
        unsigned long long p = sv[i];
        uint32_t key = (uint32_t)(p >> 32);
        uint32_t bt = (key & 0x80000000u) ? (key & 0x7FFFFFFFu) : ~key;
        float v = __uint_as_float(bt);
        float d = v - mx;
        float e = expf(d), f = expf(0.2f * d);
        fe[i] = e; ff[i] = f;
        s2c[i] = v;
        perm[i] = (int)(p & 0xFFFFFFFFu);
    }
    __syncthreads();

    {   // scans: thread owns elems {2t, 2t+1}; results kept in smem only
        int i0 = 2 * tid, i1 = 2 * tid + 1;
        float e0 = (i0 < NN) ? fe[i0] : 0.f, e1 = (i1 < NN) ? fe[i1] : 0.f;
        float f0 = (i0 < NN) ? ff[i0] : 0.f, f1 = (i1 < NN) ? ff[i1] : 0.f;
        float le = e0 + e1, lf = f0 + f1;
        float eI = le, fI = lf;
#pragma unroll
        for (int off = 1; off < 32; off <<= 1) {
            float a = __shfl_up_sync(0xffffffffu, eI, off);
            float bb = __shfl_up_sync(0xffffffffu, fI, off);
            if (lane >= off) { eI += a; fI += bb; }
        }
        if (lane == 31) { wsE[wrp] = eI; wsF[wrp] = fI; }
        __syncthreads();
        if (tid == 0) {
            float a = 0.f, bb = 0.f;
            for (int w = 0; w < 32; w++) { a += wsE[w]; wsE[w] = a; bb += wsF[w]; wsF[w] = bb; }
        }
        __syncthreads();
        float baseE = (wrp > 0) ? wsE[wrp-1] : 0.f;
        float baseF = (wrp > 0) ? wsF[wrp-1] : 0.f;
        float eexcl = baseE + (eI - le);
        float fexcl = baseF + (fI - lf);
        float totE = wsE[31], totF = wsF[31];
        if (i0 < NN) { sF2[i0] = fexcl;      sE2[i0] = totE - eexcl; }
        if (i1 < NN) { sF2[i1] = fexcl + f0; sE2[i1] = totE - (eexcl + e0); }
        if (tid == 0) { sF2[NN] = totF; sE2[NN] = 0.f; }
    }
    __syncthreads();

    // per-n: k + hoisted E1/F1/ivd
    if (tid < NN) {
        int n = tid;
        float s1v = s1[bh*NN + n];
        float thr = -s1v;
        int lo = 0, hi = NN;
        while (lo < hi) {
            int mid = (lo + hi) >> 1;
            if (s2c[mid] > thr) hi = mid; else lo = mid + 1;
        }
        float u = s1v + mx;
        float rm = u > 0.f ? u : 0.2f * u;
        float E1 = expf(u - rm), F1 = expf(0.2f * u - rm);
        float den = E1 * sE2[lo] + F1 * sF2[lo];
        g_kofn[bh*NN + n] = lo;
        g_E1[bh*NN + n] = E1;
        g_F1[bh*NN + n] = F1;
        g_ivd[bh*NN + n] = 1.f / den;
    }
    __syncthreads();

    // ---- phase B: 16 chunks x 64 o; chunk sums then interleaved sweeps ----
    const int c = tid >> 6, o = tid & 63;
    const float* whb = Wh + (size_t)b * NN * FDIM + h * HID + o;

    float cF = 0.f, cE = 0.f;
#pragma unroll 8
    for (int j = 0; j < CH; j++) {
        int i = c*CH + j;
        float w = whb[(size_t)perm[i] * FDIM];
        cF += ff[i] * w;
        cE += fe[i] * w;
    }
    chF[c*HID + o] = cF;
    chE[c*HID + o] = cE;
    __syncthreads();

    float accF = 0.f, accE = 0.f;
    for (int c2 = 0; c2 < c; c2++)       accF += chF[c2*HID + o];
    for (int c2 = c + 1; c2 < NCH; c2++) accE += chE[c2*HID + o];

    size_t base2 = ((size_t)bh*(NN+1))*HID + o;
#pragma unroll 4
    for (int j = 0; j < CH; j++) {
        int iF = c*CH + j;
        int iB = c*CH + (CH - 1 - j);
        float wF = whb[(size_t)perm[iF] * FDIM];
        float wB = whb[(size_t)perm[iB] * FDIM];
        g_PreF[base2 + (size_t)iF*HID] = accF;
        accF += ff[iF] * wF;
        accE += fe[iB] * wB;
        g_SufE[base2 + (size_t)iB*HID] = accE;
    }
    if (c == NCH - 1) {
        g_PreF[base2 + (size_t)NN*HID] = accF;
        g_SufE[base2 + (size_t)NN*HID] = 0.f;
    }
}

// Pure streaming combine: no transcendentals, float4 I/O. Output PRE-ROUNDED.
__global__ __launch_bounds__(256)
void apply_attn(float* __restrict__ out) {
    int bh = blockIdx.y, h = bh % NH, b = bh / NH;
    int n = blockIdx.x * 16 + (threadIdx.x >> 4);
    int o4 = (threadIdx.x & 15) * 4;
    int gi = bh * NN + n;
    float E1 = g_E1[gi], F1 = g_F1[gi], ivd = g_ivd[gi];
    int k = g_kofn[gi];
    size_t idx = ((size_t)bh*(NN+1) + k)*HID + o4;
    float4 S = *(const float4*)&g_SufE[idx];
    float4 P = *(const float4*)&g_PreF[idx];
    float4 v;
    v.x = rnd_tf32((E1 * S.x + F1 * P.x) * ivd);
    v.y = rnd_tf32((E1 * S.y + F1 * P.y) * ivd);
    v.z = rnd_tf32((E1 * S.z + F1 * P.z) * ivd);
    v.w = rnd_tf32((E1 * S.w + F1 * P.w) * ivd);
    *(float4*)&out[((size_t)(b*NN + n))*FDIM + h*HID + o4] = v;
}

static void run_gat_layer(const float* hin, const float* Bt, const float* att,
                          float* Wh, float* hout, int K) {
    float *s1, *s2;
    cudaGetSymbolAddress((void**)&s1, g_s1);
    cudaGetSymbolAddress((void**)&s2, g_s2);
    tf32_gemm<<<dim3(BN/128, FDIM/128), 256>>>(hin, Bt, nullptr, Wh, FDIM, K, att, s1, s2);
    prep_scan<<<BH, 1024>>>(s2, s1, Wh);
    apply_attn<<<dim3(NN/16, BH), 256>>>(hout);
}

extern "C" void kernel_launch(void* const* d_in, const int* in_sizes, int n_in,
                              void* d_out, int out_size) {
    const float* x    = (const float*)d_in[0];
    const float* ip_w = (const float*)d_in[1];
    const float* ip_b = (const float*)d_in[2];
    const float* w0   = (const float*)d_in[3];
    const float* a0   = (const float*)d_in[4];
    const float* w1   = (const float*)d_in[5];
    const float* a1   = (const float*)d_in[6];
    const float* pw   = (const float*)d_in[7];
    const float* pb   = (const float*)d_in[8];
    float* out = (float*)d_out;

    float *h0, *Wh, *hc1, *hc2, *B0t, *B1t, *pwT;
    cudaGetSymbolAddress((void**)&h0,  g_h0);
    cudaGetSymbolAddress((void**)&Wh,  g_Wh);
    cudaGetSymbolAddress((void**)&hc1, g_hc1);
    cudaGetSymbolAddress((void**)&hc2, g_hc2);
    cudaGetSymbolAddress((void**)&B0t, g_B0t);
    cudaGetSymbolAddress((void**)&B1t, g_B1t);
    cudaGetSymbolAddress((void**)&pwT, g_pwT);

    prep_B<<<512, 256>>>(w0, w1, pw);

    // input projection: h0 = x @ ip_w + ip_b  (h0 stored tf32-rounded)
    sgemm<<<dim3(BN/64, HID/64), 256>>>(x, ip_w, ip_b, h0, BN, HID, INDIM);

    run_gat_layer(h0,  B0t, a0, Wh, hc1, HID);   // GAT layer 0
    run_gat_layer(hc1, B1t, a1, Wh, hc2, FDIM);  // GAT layer 1

    // output projection: N=EMB=128 -> one N-tile
    tf32_gemm<<<dim3(BN/128, EMB/128), 256>>>(hc2, pwT, pb, out, EMB, FDIM,
                                              nullptr, nullptr, nullptr);
}